// round 14
// baseline (speedup 1.0000x reference)
#include <cuda_runtime.h>
#include <cuda_bf16.h>
#include <math.h>

#define BATCH 32
#define LQ 1024
#define LA 1024
#define HDIM 512
#define HD2 (HDIM / 2)          // 256 b32 (bf16x2) per row

#define BM 128
#define BN 128
#define BK 32                   // bf16 elements per k-tile
#define NSTAGE 3
#define SROW 24                 // smem row stride in b32 (16 data + 8 pad)
#define TILE_U32 (128 * SROW)   // 3072 u32 = 12 KB
#define NKT (HDIM / BK)         // 16

// Scratch (device globals: allocation inside kernel_launch is forbidden)
// bf16x2 packed, k-pair-permuted within each 16-element k-group:
//   pair p (k=2p,2p+1) -> b32 slot: p<4 ? 2p : 2(p-4)+1
__device__ unsigned g_qU[(size_t)BATCH * LQ * HD2];   // 32 MB (permuted bf16)
__device__ unsigned g_qt[(size_t)BATCH * LQ * HD2];   // 32 MB
__device__ unsigned g_at[(size_t)BATCH * LA * HD2];   // 32 MB
__device__ unsigned g_Ut[(size_t)HDIM * HD2];         // U transposed [n][k]
__device__ float    g_rowAtt[BATCH * LQ];
__device__ unsigned g_colMaxBits[BATCH * LA];         // float bits, >= 0
__device__ float    g_colSum[BATCH * LA];

// ---------------------------------------------------------------------------
__device__ __forceinline__ unsigned pack_bf16(float lo, float hi) {
    unsigned r;
    asm("cvt.rn.bf16x2.f32 %0, %1, %2;" : "=r"(r) : "f"(hi), "f"(lo));
    return r;
}

__device__ __forceinline__ void mma_bf16(float* d, const unsigned* a, const unsigned* b) {
    asm volatile(
        "mma.sync.aligned.m16n8k16.row.col.f32.bf16.bf16.f32 "
        "{%0,%1,%2,%3}, {%4,%5,%6,%7}, {%8,%9}, {%0,%1,%2,%3};\n"
        : "+f"(d[0]), "+f"(d[1]), "+f"(d[2]), "+f"(d[3])
        : "r"(a[0]), "r"(a[1]), "r"(a[2]), "r"(a[3]), "r"(b[0]), "r"(b[1]));
}

__device__ __forceinline__ void cp_async16(void* smem_ptr, const void* gmem) {
    unsigned s = (unsigned)__cvta_generic_to_shared(smem_ptr);
    asm volatile("cp.async.cg.shared.global [%0], [%1], 16;\n" :: "r"(s), "l"(gmem));
}
#define CP_COMMIT() asm volatile("cp.async.commit_group;\n" ::: "memory")
#define CP_WAIT()   asm volatile("cp.async.wait_group 1;\n" ::: "memory")

// Tile load: 128 rows x 16 b32 (64B) from [row][k] bf16 global; 128 threads
__device__ __forceinline__ void load_tile_async(unsigned* sm, const unsigned* g, int tid) {
    #pragma unroll
    for (int i = 0; i < 4; i++) {
        int c = tid + i * 128;         // 0..511
        int row = c >> 2, kc = c & 3;  // 4 chunks of 16B per row
        cp_async16(sm + row * SROW + kc * 4, g + (size_t)row * HD2 + kc * 4);
    }
}

// mma over one BK=32 tile: warp tile 64x64 (warp grid 2x2), operands bf16
// [row][k] k-pair-permuted. A frags cached per ks, reused across 8 nt.
__device__ __forceinline__ void compute_rr(const unsigned* sA, const unsigned* sB,
                                           float acc[4][8][4], int wm, int wn, int lane) {
    const int c2 = 2 * (lane & 3);
    const int g4 = lane >> 2;
    #pragma unroll
    for (int ks = 0; ks < 2; ks++) {
        const int ko = ks * 8 + c2;
        uint2 alo[4], ahi[4];
        #pragma unroll
        for (int mt = 0; mt < 4; mt++) {
            int row = wm * 64 + mt * 16 + g4;
            alo[mt] = *(const uint2*)(sA + row * SROW + ko);
            ahi[mt] = *(const uint2*)(sA + (row + 8) * SROW + ko);
        }
        #pragma unroll
        for (int nt = 0; nt < 8; nt++) {
            int col = wn * 64 + nt * 8 + g4;
            uint2 bv = *(const uint2*)(sB + col * SROW + ko);
            unsigned bfr[2] = {bv.x, bv.y};
            #pragma unroll
            for (int mt = 0; mt < 4; mt++) {
                unsigned afr[4] = {alo[mt].x, ahi[mt].x, alo[mt].y, ahi[mt].y};
                mma_bf16(acc[mt][nt], afr, bfr);
            }
        }
    }
}

// ---------------------------------------------------------------------------
// Kernel 0a: zero col-stat accumulators and the output buffer
// ---------------------------------------------------------------------------
__global__ void init_stats_kernel(float* out, int out_n) {
    int i = blockIdx.x * blockDim.x + threadIdx.x;
    if (i < BATCH * LA) {
        g_colMaxBits[i] = 0u;
        g_colSum[i] = 0.0f;
    }
    if (i < out_n) out[i] = 0.0f;
}

// ---------------------------------------------------------------------------
// Kernel 0b: convert q, a -> bf16, k-pair-permuted
// ---------------------------------------------------------------------------
#define NGQ (BATCH * LQ * HDIM / 16)
#define NGA (BATCH * LA * HDIM / 16)

__global__ __launch_bounds__(256) void convert_qa_kernel(const float* __restrict__ q,
                                                         const float* __restrict__ a) {
    int stride = gridDim.x * blockDim.x;
    for (int i = blockIdx.x * blockDim.x + threadIdx.x; i < NGQ + NGA; i += stride) {
        const float4* src;
        uint4* dst;
        if (i < NGQ) {
            src = (const float4*)q + (size_t)i * 4;
            dst = (uint4*)g_qt + (size_t)i * 2;
        } else {
            int j = i - NGQ;
            src = (const float4*)a + (size_t)j * 4;
            dst = (uint4*)g_at + (size_t)j * 2;
        }
        float4 v0 = src[0], v1 = src[1], v2 = src[2], v3 = src[3];
        uint4 w0, w1;
        w0.x = pack_bf16(v0.x, v0.y);   // slot0 = p0
        w0.y = pack_bf16(v2.x, v2.y);   // slot1 = p4
        w0.z = pack_bf16(v0.z, v0.w);   // slot2 = p1
        w0.w = pack_bf16(v2.z, v2.w);   // slot3 = p5
        w1.x = pack_bf16(v1.x, v1.y);   // slot4 = p2
        w1.y = pack_bf16(v3.x, v3.y);   // slot5 = p6
        w1.z = pack_bf16(v1.z, v1.w);   // slot6 = p3
        w1.w = pack_bf16(v3.z, v3.w);   // slot7 = p7
        dst[0] = w0;
        dst[1] = w1;
    }
}

// ---------------------------------------------------------------------------
// Kernel 0c: U [k][n] fp32 -> g_Ut [n][k] bf16, k-pair-permuted
// ---------------------------------------------------------------------------
__global__ __launch_bounds__(256) void convert_U_kernel(const float* __restrict__ U) {
    int i = blockIdx.x * blockDim.x + threadIdx.x;
    if (i >= HDIM * HD2) return;
    int n = i >> 8;
    int o = i & 255;
    int g16 = o >> 3, s = o & 7;
    int p = (s & 1) ? 4 + (s >> 1) : (s >> 1);
    int k0 = g16 * 16 + 2 * p;
    g_Ut[i] = pack_bf16(U[(size_t)k0 * HDIM + n], U[(size_t)(k0 + 1) * HDIM + n]);
}

// ---------------------------------------------------------------------------
// Kernel 1: qU = q @ U  (bf16 mma, 64x64 warp tiles, 4 warps, 3-stage pipe)
// ---------------------------------------------------------------------------
__global__ __launch_bounds__(128, 3) void gemm_qU_tc() {
    extern __shared__ unsigned dsm[];
    unsigned* sA = dsm;                          // [NSTAGE][TILE_U32]
    unsigned* sB = dsm + NSTAGE * TILE_U32;

    const int tid  = threadIdx.x;
    const int lane = tid & 31;
    const int w    = tid >> 5;          // 0..3
    const int wm   = w >> 1;
    const int wn   = w & 1;
    const int m0   = blockIdx.y * BM;
    const int n0   = blockIdx.x * BN;

    const unsigned* gA = g_qt + (size_t)m0 * HD2;
    const unsigned* gB = g_Ut + (size_t)n0 * HD2;

    float acc[4][8][4] = {};

    #pragma unroll
    for (int s = 0; s < NSTAGE - 1; s++) {
        load_tile_async(sA + s * TILE_U32, gA + s * 16, tid);
        load_tile_async(sB + s * TILE_U32, gB + s * 16, tid);
        CP_COMMIT();
    }

    for (int kt = 0; kt < NKT; kt++) {
        CP_WAIT();
        __syncthreads();
        int pf = kt + NSTAGE - 1;
        if (pf < NKT) {
            load_tile_async(sA + (pf % NSTAGE) * TILE_U32, gA + pf * 16, tid);
            load_tile_async(sB + (pf % NSTAGE) * TILE_U32, gB + pf * 16, tid);
        }
        CP_COMMIT();
        compute_rr(sA + (kt % NSTAGE) * TILE_U32, sB + (kt % NSTAGE) * TILE_U32,
                   acc, wm, wn, lane);
    }

    // epilogue: write g_qU as bf16, k-pair-permuted along n
    #pragma unroll
    for (int mt = 0; mt < 4; mt++) {
        int row = m0 + wm * 64 + mt * 16 + (lane >> 2);
        #pragma unroll
        for (int nt = 0; nt < 8; nt++) {
            // col = n0 + wn*64 + nt*8 + 2c(+1); within-16 pair p = 4*(nt&1)+c
            // -> permuted slot base (n0+wn*64+(nt>>1)*16)/2 + 2c + (nt&1)
            int gb = ((n0 + wn * 64) >> 1) + (nt >> 1) * 8 + 2 * (lane & 3) + (nt & 1);
            g_qU[(size_t)row * HD2 + gb]       = pack_bf16(acc[mt][nt][0], acc[mt][nt][1]);
            g_qU[(size_t)(row + 8) * HD2 + gb] = pack_bf16(acc[mt][nt][2], acc[mt][nt][3]);
        }
    }
}

// ---------------------------------------------------------------------------
// Kernel 2: fused X = qU @ a^T + sigmoid/exp + row & col stats
// 64x64 warp tiles, 4 warps; flat 128-tile pipeline over (j0 x kt)
// ---------------------------------------------------------------------------
__global__ __launch_bounds__(128, 3) void fused_X_tc(const float* __restrict__ q_mask,
                                                     const float* __restrict__ a_mask) {
    extern __shared__ unsigned dsm[];
    unsigned* sA = dsm;
    unsigned* sB = dsm + NSTAGE * TILE_U32;

    const int tid  = threadIdx.x;
    const int lane = tid & 31;
    const int w    = tid >> 5;
    const int wm   = w >> 1;
    const int wn   = w & 1;
    const int b    = blockIdx.y;
    const int i0   = blockIdx.x * BM;

    const unsigned* qUb = g_qU + ((size_t)b * LQ + i0) * HD2;
    const unsigned* ab  = g_at + (size_t)b * LA * HD2;

    float rowMax[4][2] = {};
    float rowSum[4][2] = {};
    float acc[4][8][4] = {};

    const int NT = (LA / BN) * NKT;   // 128 total tiles

    #pragma unroll
    for (int s = 0; s < NSTAGE - 1; s++) {
        load_tile_async(sA + s * TILE_U32, qUb + s * 16, tid);
        load_tile_async(sB + s * TILE_U32, ab + s * 16, tid);   // j = 0
        CP_COMMIT();
    }

    for (int t = 0; t < NT; t++) {
        CP_WAIT();
        __syncthreads();
        int pf = t + NSTAGE - 1;
        if (pf < NT) {
            int pj = pf >> 4, pk = pf & 15;
            load_tile_async(sA + (pf % NSTAGE) * TILE_U32, qUb + pk * 16, tid);
            load_tile_async(sB + (pf % NSTAGE) * TILE_U32,
                            ab + (size_t)pj * BN * HD2 + pk * 16, tid);
        }
        CP_COMMIT();
        compute_rr(sA + (t % NSTAGE) * TILE_U32, sB + (t % NSTAGE) * TILE_U32,
                   acc, wm, wn, lane);

        if ((t & 15) == 15) {
            // ---- epilogue for j0 = (t>>4)*BN ----
            const int j0 = (t >> 4) * BN;
            // scratch aliases the just-consumed stage; next write to this stage
            // happens at iteration t+1's prefetch, after a __syncthreads
            float* redM = (float*)(sA + (t % NSTAGE) * TILE_U32);
            float* redS = redM + 256;

            float cMax[8][2] = {};
            float cSum[8][2] = {};

            #pragma unroll
            for (int mt = 0; mt < 4; mt++) {
                int r = i0 + wm * 64 + mt * 16 + (lane >> 2);
                float qm0 = __ldg(&q_mask[b * LQ + r]);
                float qm1 = __ldg(&q_mask[b * LQ + r + 8]);
                #pragma unroll
                for (int nt = 0; nt < 8; nt++) {
                    int c = j0 + wn * 64 + nt * 8 + (lane & 3) * 2;
                    float am0 = __ldg(&a_mask[b * LA + c]);
                    float am1 = __ldg(&a_mask[b * LA + c + 1]);
                    #pragma unroll
                    for (int e = 0; e < 4; e++) {
                        float X = acc[mt][nt][e];
                        float qm = (e >> 1) ? qm1 : qm0;
                        float am = (e & 1) ? am1 : am0;
                        bool valid = (qm * am) > 0.0f;
                        float I = valid ? __fdividef(1.0f, 1.0f + __expf(-X)) : 0.0f;
                        float ee = __expf(I);
                        rowMax[mt][e >> 1] = fmaxf(rowMax[mt][e >> 1], I);
                        rowSum[mt][e >> 1] += ee;
                        cMax[nt][e & 1] = fmaxf(cMax[nt][e & 1], I);
                        cSum[nt][e & 1] += ee;
                        acc[mt][nt][e] = 0.0f;   // reset for next j-tile
                    }
                }
            }

            __syncthreads();   // stage fully consumed before scratch reuse
            #pragma unroll
            for (int nt = 0; nt < 8; nt++) {
                #pragma unroll
                for (int j = 0; j < 2; j++) {
                    float m = cMax[nt][j], s = cSum[nt][j];
                    #pragma unroll
                    for (int off = 4; off < 32; off <<= 1) {
                        m = fmaxf(m, __shfl_xor_sync(0xffffffffu, m, off));
                        s += __shfl_xor_sync(0xffffffffu, s, off);
                    }
                    if (lane < 4) {
                        int colL = wn * 64 + nt * 8 + 2 * lane + j;
                        redM[wm * 128 + colL] = m;
                        redS[wm * 128 + colL] = s;
                    }
                }
            }
            __syncthreads();
            if (tid < 128) {
                float m = fmaxf(redM[tid], redM[128 + tid]);
                float s = redS[tid] + redS[128 + tid];
                int cj = b * LA + j0 + tid;
                atomicMax(&g_colMaxBits[cj], __float_as_uint(m));
                atomicAdd(&g_colSum[cj], s);
            }
            __syncthreads();   // scratch released before next iteration's loads
        }
    }

    // ---- final row reduction ----
    {
        float* redM = (float*)dsm;
        float* redS = redM + 256;
        #pragma unroll
        for (int mt = 0; mt < 4; mt++) {
            #pragma unroll
            for (int e = 0; e < 2; e++) {
                float m = rowMax[mt][e], s = rowSum[mt][e];
                #pragma unroll
                for (int off = 1; off < 4; off <<= 1) {
                    m = fmaxf(m, __shfl_xor_sync(0xffffffffu, m, off));
                    s += __shfl_xor_sync(0xffffffffu, s, off);
                }
                if ((lane & 3) == 0) {
                    int rowL = wm * 64 + mt * 16 + (lane >> 2) + e * 8;
                    redM[wn * 128 + rowL] = m;
                    redS[wn * 128 + rowL] = s;
                }
            }
        }
        __syncthreads();
        if (tid < 128) {
            float m = fmaxf(redM[tid], redM[128 + tid]);
            float s = redS[tid] + redS[128 + tid];
            g_rowAtt[b * LQ + i0 + tid] = __expf(m) / s;
        }
    }
}

// ---------------------------------------------------------------------------
// Kernel 3: weighted reductions, 8 L-segments with atomicAdd (exact fp32 q/a)
// ---------------------------------------------------------------------------
__global__ __launch_bounds__(512) void finalize_tc(const float* __restrict__ q,
                                                   const float* __restrict__ a,
                                                   float* __restrict__ out) {
    __shared__ float attS[128];
    const int b     = blockIdx.x;
    const int which = blockIdx.y;
    const int seg   = blockIdx.z;   // 0..7
    const int h     = threadIdx.x;
    const int l0    = seg * 128;

    if (h < 128) {
        int l = l0 + h;
        if (which == 0) {
            attS[h] = g_rowAtt[b * LQ + l];
        } else {
            float m = __uint_as_float(g_colMaxBits[b * LA + l]);
            attS[h] = __expf(m) / g_colSum[b * LA + l];
        }
    }
    __syncthreads();

    const float* src = ((which == 0) ? q : a) + (size_t)b * LQ * HDIM + (size_t)l0 * HDIM;

    float a0 = 0.f, a1 = 0.f, a2 = 0.f, a3 = 0.f;
    #pragma unroll 4
    for (int l = 0; l < 128; l += 4) {
        a0 = fmaf(src[(size_t)(l + 0) * HDIM + h], attS[l + 0], a0);
        a1 = fmaf(src[(size_t)(l + 1) * HDIM + h], attS[l + 1], a1);
        a2 = fmaf(src[(size_t)(l + 2) * HDIM + h], attS[l + 2], a2);
        a3 = fmaf(src[(size_t)(l + 3) * HDIM + h], attS[l + 3], a3);
    }
    atomicAdd(&out[(size_t)which * BATCH * HDIM + b * HDIM + h], (a0 + a1) + (a2 + a3));
}

// ---------------------------------------------------------------------------
extern "C" void kernel_launch(void* const* d_in, const int* in_sizes, int n_in,
                              void* d_out, int out_size) {
    const float* q      = (const float*)d_in[0];
    const float* a      = (const float*)d_in[1];
    const float* U      = (const float*)d_in[2];
    const float* q_mask = (const float*)d_in[3];
    const float* a_mask = (const float*)d_in[4];
    float* out = (float*)d_out;

    const int smem_sz = NSTAGE * 2 * TILE_U32 * sizeof(unsigned);   // 73728
    cudaFuncSetAttribute(gemm_qU_tc, cudaFuncAttributeMaxDynamicSharedMemorySize, smem_sz);
    cudaFuncSetAttribute(fused_X_tc, cudaFuncAttributeMaxDynamicSharedMemorySize, smem_sz);

    init_stats_kernel<<<(BATCH * LA + 255) / 256, 256>>>(out, out_size);
    convert_qa_kernel<<<4096, 256>>>(q, a);
    convert_U_kernel<<<(HDIM * HD2 + 255) / 256, 256>>>(U);

    dim3 g1(HDIM / BN, (BATCH * LQ) / BM);   // (4, 256)
    gemm_qU_tc<<<g1, 128, smem_sz>>>();

    dim3 g2(LQ / BM, BATCH);                 // (8, 32)
    fused_X_tc<<<g2, 128, smem_sz>>>(q_mask, a_mask);

    dim3 g3(BATCH, 2, 8);
    finalize_tc<<<g3, 512>>>(q, a, out);
}

// round 15
// speedup vs baseline: 1.0176x; 1.0176x over previous
#include <cuda_runtime.h>
#include <cuda_bf16.h>
#include <math.h>

#define BATCH 32
#define LQ 1024
#define LA 1024
#define HDIM 512
#define HD2 (HDIM / 2)          // 256 b32 (bf16x2) per row

#define BM 128
#define BN 128
#define NSTAGE 3
#define CHUNK1_OFF 2064         // sub-tile 1 offset (2048 data + 16 stagger)
#define STAGE_U32 4112          // 2 sub-tiles of 128x16 b32 (+16 stagger)
#define NKT64 (HDIM / 64)       // 8 k64-stages per 512-K pass

// Scratch (device globals: allocation inside kernel_launch is forbidden)
// bf16x2 packed; within each 32-k chunk (16 b32) pairs are stored as
// [p0 p4 p8 p12 | p1 p5 p9 p13 | p2 p6 p10 p14 | p3 p7 p11 p15]
// so slot(pp) = 4*(pp&3) + (pp>>2). One uint4 at 4c = frag pairs
// {c, c+4, 8+c, 12+c} = both k16-mma fragments for lane group c.
__device__ unsigned g_qU[(size_t)BATCH * LQ * HD2];   // 32 MB
__device__ unsigned g_qt[(size_t)BATCH * LQ * HD2];   // 32 MB
__device__ unsigned g_at[(size_t)BATCH * LA * HD2];   // 32 MB
__device__ unsigned g_Ut[(size_t)HDIM * HD2];         // U transposed [n][k]
__device__ float    g_rowAtt[BATCH * LQ];
__device__ unsigned g_colMaxBits[BATCH * LA];         // float bits, >= 0
__device__ float    g_colSum[BATCH * LA];

// ---------------------------------------------------------------------------
__device__ __forceinline__ unsigned pack_bf16(float lo, float hi) {
    unsigned r;
    asm("cvt.rn.bf16x2.f32 %0, %1, %2;" : "=r"(r) : "f"(hi), "f"(lo));
    return r;
}

__device__ __forceinline__ void mma_bf16(float* d, const unsigned* a, const unsigned* b) {
    asm volatile(
        "mma.sync.aligned.m16n8k16.row.col.f32.bf16.bf16.f32 "
        "{%0,%1,%2,%3}, {%4,%5,%6,%7}, {%8,%9}, {%0,%1,%2,%3};\n"
        : "+f"(d[0]), "+f"(d[1]), "+f"(d[2]), "+f"(d[3])
        : "r"(a[0]), "r"(a[1]), "r"(a[2]), "r"(a[3]), "r"(b[0]), "r"(b[1]));
}

__device__ __forceinline__ void cp_async16(void* smem_ptr, const void* gmem) {
    unsigned s = (unsigned)__cvta_generic_to_shared(smem_ptr);
    asm volatile("cp.async.cg.shared.global [%0], [%1], 16;\n" :: "r"(s), "l"(gmem));
}
#define CP_COMMIT() asm volatile("cp.async.commit_group;\n" ::: "memory")
#define CP_WAIT1()  asm volatile("cp.async.wait_group 1;\n" ::: "memory")

// k64-stage load: 128 rows x 32 b32 (two 16-b32 chunks), 256 threads x 4 chunks
__device__ __forceinline__ void load_stage_async(unsigned* sm, const unsigned* g, int tid) {
    #pragma unroll
    for (int i = 0; i < 4; i++) {
        int c = tid + i * 256;          // 0..1023
        int row = c >> 3, kc = c & 7;   // 8 x 16B per row
        cp_async16(sm + (kc >> 2) * CHUNK1_OFF + row * 16 + (kc & 3) * 4,
                   g + (size_t)row * HD2 + kc * 4);
    }
}

// mma over one k64 stage (2 chunks of 32 k each); warp tile 64x32 (grid 2x4)
__device__ __forceinline__ void compute_stage(const unsigned* sA, const unsigned* sB,
                                              float acc[4][4][4], int wm, int wn, int lane) {
    const int c4 = 4 * (lane & 3);
    const int g4 = lane >> 2;
    #pragma unroll
    for (int kcc = 0; kcc < 2; kcc++) {
        const int base = kcc * CHUNK1_OFF + c4;
        uint4 alo[4], ahi[4];
        #pragma unroll
        for (int mt = 0; mt < 4; mt++) {
            int row = wm * 64 + mt * 16 + g4;
            alo[mt] = *(const uint4*)(sA + base + row * 16);
            ahi[mt] = *(const uint4*)(sA + base + (row + 8) * 16);
        }
        #pragma unroll
        for (int nt = 0; nt < 4; nt++) {
            int col = wn * 32 + nt * 8 + g4;
            uint4 bv = *(const uint4*)(sB + base + col * 16);
            unsigned b0[2] = {bv.x, bv.y};
            unsigned b1[2] = {bv.z, bv.w};
            #pragma unroll
            for (int mt = 0; mt < 4; mt++) {
                unsigned a0[4] = {alo[mt].x, ahi[mt].x, alo[mt].y, ahi[mt].y};
                mma_bf16(acc[mt][nt], a0, b0);
                unsigned a1[4] = {alo[mt].z, ahi[mt].z, alo[mt].w, ahi[mt].w};
                mma_bf16(acc[mt][nt], a1, b1);
            }
        }
    }
}

// ---------------------------------------------------------------------------
// Kernel 0a: zero col-stat accumulators and the output buffer
// ---------------------------------------------------------------------------
__global__ void init_stats_kernel(float* out, int out_n) {
    int i = blockIdx.x * blockDim.x + threadIdx.x;
    if (i < BATCH * LA) {
        g_colMaxBits[i] = 0u;
        g_colSum[i] = 0.0f;
    }
    if (i < out_n) out[i] = 0.0f;
}

// ---------------------------------------------------------------------------
// Kernel 0b: convert q, a -> bf16, chunk-interleaved. One thread per 32-k chunk.
// ---------------------------------------------------------------------------
#define NCQ (BATCH * LQ * HDIM / 32)   // 524288
#define NCA (BATCH * LA * HDIM / 32)

__global__ __launch_bounds__(256) void convert_qa_kernel(const float* __restrict__ q,
                                                         const float* __restrict__ a) {
    int stride = gridDim.x * blockDim.x;
    for (int i = blockIdx.x * blockDim.x + threadIdx.x; i < NCQ + NCA; i += stride) {
        const float4* src;
        uint4* dst;
        if (i < NCQ) {
            src = (const float4*)q + (size_t)i * 8;
            dst = (uint4*)g_qt + (size_t)i * 4;
        } else {
            int j = i - NCQ;
            src = (const float4*)a + (size_t)j * 8;
            dst = (uint4*)g_at + (size_t)j * 4;
        }
        float4 v0 = src[0], v1 = src[1], v2 = src[2], v3 = src[3];
        float4 v4 = src[4], v5 = src[5], v6 = src[6], v7 = src[7];
        uint4 w0, w1, w2, w3;
        // slots 0-3: pairs p0 p4 p8 p12
        w0.x = pack_bf16(v0.x, v0.y); w0.y = pack_bf16(v2.x, v2.y);
        w0.z = pack_bf16(v4.x, v4.y); w0.w = pack_bf16(v6.x, v6.y);
        // slots 4-7: pairs p1 p5 p9 p13
        w1.x = pack_bf16(v0.z, v0.w); w1.y = pack_bf16(v2.z, v2.w);
        w1.z = pack_bf16(v4.z, v4.w); w1.w = pack_bf16(v6.z, v6.w);
        // slots 8-11: pairs p2 p6 p10 p14
        w2.x = pack_bf16(v1.x, v1.y); w2.y = pack_bf16(v3.x, v3.y);
        w2.z = pack_bf16(v5.x, v5.y); w2.w = pack_bf16(v7.x, v7.y);
        // slots 12-15: pairs p3 p7 p11 p15
        w3.x = pack_bf16(v1.z, v1.w); w3.y = pack_bf16(v3.z, v3.w);
        w3.z = pack_bf16(v5.z, v5.w); w3.w = pack_bf16(v7.z, v7.w);
        dst[0] = w0; dst[1] = w1; dst[2] = w2; dst[3] = w3;
    }
}

// ---------------------------------------------------------------------------
// Kernel 0c: U [k][n] fp32 -> g_Ut [n][k] bf16, chunk-interleaved
// ---------------------------------------------------------------------------
__global__ __launch_bounds__(256) void convert_U_kernel(const float* __restrict__ U) {
    int i = blockIdx.x * blockDim.x + threadIdx.x;
    if (i >= HDIM * HD2) return;
    int n = i >> 8;
    int o = i & 255;
    int chunk = o >> 4, s = o & 15;
    int p = (s >> 2) + 4 * (s & 3);      // slot -> pair
    int k0 = chunk * 32 + 2 * p;
    g_Ut[i] = pack_bf16(U[(size_t)k0 * HDIM + n], U[(size_t)(k0 + 1) * HDIM + n]);
}

// ---------------------------------------------------------------------------
// Kernel 1: qU = q @ U  (bf16 mma, 64x32 warp tiles, 8 warps, BK=64 stages)
// ---------------------------------------------------------------------------
__global__ __launch_bounds__(256, 2) void gemm_qU_tc() {
    extern __shared__ unsigned dsm[];
    unsigned* sA = dsm;                           // [NSTAGE][STAGE_U32]
    unsigned* sB = dsm + NSTAGE * STAGE_U32;

    const int tid  = threadIdx.x;
    const int lane = tid & 31;
    const int wm   = (tid >> 5) >> 2;
    const int wn   = (tid >> 5) & 3;
    const int m0   = blockIdx.y * BM;
    const int n0   = blockIdx.x * BN;

    const unsigned* gA = g_qt + (size_t)m0 * HD2;
    const unsigned* gB = g_Ut + (size_t)n0 * HD2;

    float acc[4][4][4] = {};

    #pragma unroll
    for (int s = 0; s < NSTAGE - 1; s++) {
        load_stage_async(sA + s * STAGE_U32, gA + s * 32, tid);
        load_stage_async(sB + s * STAGE_U32, gB + s * 32, tid);
        CP_COMMIT();
    }

    for (int kt = 0; kt < NKT64; kt++) {
        CP_WAIT1();
        __syncthreads();
        int pf = kt + NSTAGE - 1;
        if (pf < NKT64) {
            load_stage_async(sA + (pf % NSTAGE) * STAGE_U32, gA + pf * 32, tid);
            load_stage_async(sB + (pf % NSTAGE) * STAGE_U32, gB + pf * 32, tid);
        }
        CP_COMMIT();
        compute_stage(sA + (kt % NSTAGE) * STAGE_U32, sB + (kt % NSTAGE) * STAGE_U32,
                      acc, wm, wn, lane);
    }

    // epilogue: write g_qU bf16 in chunk-interleaved layout along n
    // pair P = n0/2 + wn*16 + nt*4 + c -> chunk offset (n0>>1)+wn*16, slot 4c+nt
    #pragma unroll
    for (int mt = 0; mt < 4; mt++) {
        int row = m0 + wm * 64 + mt * 16 + (lane >> 2);
        #pragma unroll
        for (int nt = 0; nt < 4; nt++) {
            int gb = (n0 >> 1) + wn * 16 + 4 * (lane & 3) + nt;
            g_qU[(size_t)row * HD2 + gb]       = pack_bf16(acc[mt][nt][0], acc[mt][nt][1]);
            g_qU[(size_t)(row + 8) * HD2 + gb] = pack_bf16(acc[mt][nt][2], acc[mt][nt][3]);
        }
    }
}

// ---------------------------------------------------------------------------
// Kernel 2: fused X = qU @ a^T + sigmoid/exp + row & col stats
// flat 64-stage pipeline over (j0 x k64); epilogue every 8 stages
// ---------------------------------------------------------------------------
__global__ __launch_bounds__(256, 2) void fused_X_tc(const float* __restrict__ q_mask,
                                                     const float* __restrict__ a_mask) {
    extern __shared__ unsigned dsm[];
    unsigned* sA = dsm;
    unsigned* sB = dsm + NSTAGE * STAGE_U32;

    const int tid  = threadIdx.x;
    const int lane = tid & 31;
    const int wm   = (tid >> 5) >> 2;
    const int wn   = (tid >> 5) & 3;
    const int b    = blockIdx.y;
    const int i0   = blockIdx.x * BM;

    const unsigned* qUb = g_qU + ((size_t)b * LQ + i0) * HD2;
    const unsigned* ab  = g_at + (size_t)b * LA * HD2;

    float qm[4][2];
    #pragma unroll
    for (int mt = 0; mt < 4; mt++) {
        int r = i0 + wm * 64 + mt * 16 + (lane >> 2);
        qm[mt][0] = q_mask[b * LQ + r];
        qm[mt][1] = q_mask[b * LQ + r + 8];
    }

    float rowMax[4][2] = {};
    float rowSum[4][2] = {};
    float acc[4][4][4] = {};

    const int NT = (LA / BN) * NKT64;   // 64 stages total

    #pragma unroll
    for (int s = 0; s < NSTAGE - 1; s++) {
        load_stage_async(sA + s * STAGE_U32, qUb + s * 32, tid);
        load_stage_async(sB + s * STAGE_U32, ab + s * 32, tid);   // j = 0
        CP_COMMIT();
    }

    for (int t = 0; t < NT; t++) {
        CP_WAIT1();
        __syncthreads();
        int pf = t + NSTAGE - 1;
        if (pf < NT) {
            int pj = pf >> 3, pk = pf & 7;
            load_stage_async(sA + (pf % NSTAGE) * STAGE_U32, qUb + pk * 32, tid);
            load_stage_async(sB + (pf % NSTAGE) * STAGE_U32,
                             ab + (size_t)pj * BN * HD2 + pk * 32, tid);
        }
        CP_COMMIT();
        compute_stage(sA + (t % NSTAGE) * STAGE_U32, sB + (t % NSTAGE) * STAGE_U32,
                      acc, wm, wn, lane);

        if ((t & 7) == 7) {
            // ---- epilogue for j0 = (t>>3)*BN ----
            const int j0 = (t >> 3) * BN;
            // scratch aliases the just-consumed stage; the next write into this
            // stage is iteration t+1's prefetch, after a __syncthreads
            float* redM = (float*)(sA + (t % NSTAGE) * STAGE_U32);
            float* redS = redM + 256;

            float am[4][2];
            #pragma unroll
            for (int nt = 0; nt < 4; nt++) {
                int c = j0 + wn * 32 + nt * 8 + (lane & 3) * 2;
                am[nt][0] = __ldg(&a_mask[b * LA + c]);
                am[nt][1] = __ldg(&a_mask[b * LA + c + 1]);
            }

            float cMax[4][2] = {};
            float cSum[4][2] = {};

            #pragma unroll
            for (int mt = 0; mt < 4; mt++) {
                #pragma unroll
                for (int nt = 0; nt < 4; nt++) {
                    #pragma unroll
                    for (int e = 0; e < 4; e++) {
                        float X = acc[mt][nt][e];
                        bool valid = (qm[mt][e >> 1] * am[nt][e & 1]) > 0.0f;
                        float I = valid ? __fdividef(1.0f, 1.0f + __expf(-X)) : 0.0f;
                        float ee = __expf(I);
                        rowMax[mt][e >> 1] = fmaxf(rowMax[mt][e >> 1], I);
                        rowSum[mt][e >> 1] += ee;
                        cMax[nt][e & 1] = fmaxf(cMax[nt][e & 1], I);
                        cSum[nt][e & 1] += ee;
                        acc[mt][nt][e] = 0.0f;   // reset for next j-tile
                    }
                }
            }

            __syncthreads();   // stage fully consumed before scratch reuse
            #pragma unroll
            for (int nt = 0; nt < 4; nt++) {
                #pragma unroll
                for (int j = 0; j < 2; j++) {
                    float m = cMax[nt][j], s = cSum[nt][j];
                    #pragma unroll
                    for (int off = 4; off < 32; off <<= 1) {
                        m = fmaxf(m, __shfl_xor_sync(0xffffffffu, m, off));
                        s += __shfl_xor_sync(0xffffffffu, s, off);
                    }
                    if (lane < 4) {
                        int colL = wn * 32 + nt * 8 + 2 * lane + j;
                        redM[wm * 128 + colL] = m;
                        redS[wm * 128 + colL] = s;
                    }
                }
            }
            __syncthreads();
            if (tid < 128) {
                float m = fmaxf(redM[tid], redM[128 + tid]);
                float s = redS[tid] + redS[128 + tid];
                int cj = b * LA + j0 + tid;
                atomicMax(&g_colMaxBits[cj], __float_as_uint(m));
                atomicAdd(&g_colSum[cj], s);
            }
            __syncthreads();   // scratch released before next iteration's loads
        }
    }

    // ---- final row reduction ----
    {
        float* redM = (float*)dsm;
        float* redS = redM + 512;
        #pragma unroll
        for (int mt = 0; mt < 4; mt++) {
            #pragma unroll
            for (int e = 0; e < 2; e++) {
                float m = rowMax[mt][e], s = rowSum[mt][e];
                #pragma unroll
                for (int off = 1; off < 4; off <<= 1) {
                    m = fmaxf(m, __shfl_xor_sync(0xffffffffu, m, off));
                    s += __shfl_xor_sync(0xffffffffu, s, off);
                }
                if ((lane & 3) == 0) {
                    int rowL = wm * 64 + mt * 16 + (lane >> 2) + e * 8;
                    redM[wn * 128 + rowL] = m;
                    redS[wn * 128 + rowL] = s;
                }
            }
        }
        __syncthreads();
        if (tid < 128) {
            float m = redM[tid], s = redS[tid];
            #pragma unroll
            for (int w = 1; w < 4; w++) {
                m = fmaxf(m, redM[w * 128 + tid]);
                s += redS[w * 128 + tid];
            }
            g_rowAtt[b * LQ + i0 + tid] = __expf(m) / s;
        }
    }
}

// ---------------------------------------------------------------------------
// Kernel 3: weighted reductions, 8 L-segments with atomicAdd (exact fp32 q/a)
// ---------------------------------------------------------------------------
__global__ __launch_bounds__(512) void finalize_tc(const float* __restrict__ q,
                                                   const float* __restrict__ a,
                                                   float* __restrict__ out) {
    __shared__ float attS[128];
    const int b     = blockIdx.x;
    const int which = blockIdx.y;
    const int seg   = blockIdx.z;   // 0..7
    const int h     = threadIdx.x;
    const int l0    = seg * 128;

    if (h < 128) {
        int l = l0 + h;
        if (which == 0) {
            attS[h] = g_rowAtt[b * LQ + l];
        } else {
            float m = __uint_as_float(g_colMaxBits[b * LA + l]);
            attS[h] = __expf(m) / g_colSum[b * LA + l];
        }
    }
    __syncthreads();

    const float* src = ((which == 0) ? q : a) + (size_t)b * LQ * HDIM + (size_t)l0 * HDIM;

    float a0 = 0.f, a1 = 0.f, a2 = 0.f, a3 = 0.f;
    #pragma unroll 4
    for (int l = 0; l < 128; l += 4) {
        a0 = fmaf(src[(size_t)(l + 0) * HDIM + h], attS[l + 0], a0);
        a1 = fmaf(src[(size_t)(l + 1) * HDIM + h], attS[l + 1], a1);
        a2 = fmaf(src[(size_t)(l + 2) * HDIM + h], attS[l + 2], a2);
        a3 = fmaf(src[(size_t)(l + 3) * HDIM + h], attS[l + 3], a3);
    }
    atomicAdd(&out[(size_t)which * BATCH * HDIM + b * HDIM + h], (a0 + a1) + (a2 + a3));
}

// ---------------------------------------------------------------------------
extern "C" void kernel_launch(void* const* d_in, const int* in_sizes, int n_in,
                              void* d_out, int out_size) {
    const float* q      = (const float*)d_in[0];
    const float* a      = (const float*)d_in[1];
    const float* U      = (const float*)d_in[2];
    const float* q_mask = (const float*)d_in[3];
    const float* a_mask = (const float*)d_in[4];
    float* out = (float*)d_out;

    const int smem_sz = NSTAGE * 2 * STAGE_U32 * sizeof(unsigned);   // 98688
    cudaFuncSetAttribute(gemm_qU_tc, cudaFuncAttributeMaxDynamicSharedMemorySize, smem_sz);
    cudaFuncSetAttribute(fused_X_tc, cudaFuncAttributeMaxDynamicSharedMemorySize, smem_sz);

    init_stats_kernel<<<(BATCH * LA + 255) / 256, 256>>>(out, out_size);
    convert_qa_kernel<<<4096, 256>>>(q, a);
    convert_U_kernel<<<(HDIM * HD2 + 255) / 256, 256>>>(U);

    dim3 g1(HDIM / BN, (BATCH * LQ) / BM);   // (4, 256)
    gemm_qU_tc<<<g1, 256, smem_sz>>>();

    dim3 g2(LQ / BM, BATCH);                 // (8, 32)
    fused_X_tc<<<g2, 256, smem_sz>>>(q_mask, a_mask);

    dim3 g3(BATCH, 2, 8);
    finalize_tc<<<g3, 512>>>(q, a, out);
}

// round 17
// speedup vs baseline: 1.3340x; 1.3109x over previous
#include <cuda_runtime.h>
#include <cuda_bf16.h>
#include <math.h>

#define BATCH 32
#define LQ 1024
#define LA 1024
#define HDIM 512
#define HD2 (HDIM / 2)          // 256 b32 (bf16x2) per row

#define BM 128
#define BN 128
#define NSTAGE 5
#define STAGE_U32 2048          // 128 rows x 16 b32, exact (swizzled, no pad)
#define STAGE_BYTES 8192
#define NKT 16                  // 512 / 32

// Scratch (device globals: allocation inside kernel_launch is forbidden)
// All bf16 buffers are PLAIN [row][k] bf16x2 (no permutation; LDSM handles
// fragment distribution).
__device__ unsigned g_qU[(size_t)BATCH * LQ * HD2];   // 32 MB
__device__ unsigned g_qt[(size_t)BATCH * LQ * HD2];   // 32 MB
__device__ unsigned g_at[(size_t)BATCH * LA * HD2];   // 32 MB
__device__ unsigned g_Ut[(size_t)HDIM * HD2];         // U transposed [n][k]
__device__ float    g_rowAtt[BATCH * LQ];
__device__ unsigned g_colMaxBits[BATCH * LA];         // float bits, >= 0
__device__ float    g_colSum[BATCH * LA];

// ---------------------------------------------------------------------------
__device__ __forceinline__ unsigned pack_bf16(float lo, float hi) {
    unsigned r;
    asm("cvt.rn.bf16x2.f32 %0, %1, %2;" : "=r"(r) : "f"(hi), "f"(lo));
    return r;
}

__device__ __forceinline__ void mma_bf16(float* d, const unsigned* a, const unsigned* b) {
    asm volatile(
        "mma.sync.aligned.m16n8k16.row.col.f32.bf16.bf16.f32 "
        "{%0,%1,%2,%3}, {%4,%5,%6,%7}, {%8,%9}, {%0,%1,%2,%3};\n"
        : "+f"(d[0]), "+f"(d[1]), "+f"(d[2]), "+f"(d[3])
        : "r"(a[0]), "r"(a[1]), "r"(a[2]), "r"(a[3]), "r"(b[0]), "r"(b[1]));
}

__device__ __forceinline__ void ldsm_x4(unsigned* r, unsigned addr) {
    asm volatile("ldmatrix.sync.aligned.m8n8.x4.shared.b16 {%0,%1,%2,%3}, [%4];"
        : "=r"(r[0]), "=r"(r[1]), "=r"(r[2]), "=r"(r[3]) : "r"(addr));
}

__device__ __forceinline__ void cp_async16(void* smem_ptr, const void* gmem) {
    unsigned s = (unsigned)__cvta_generic_to_shared(smem_ptr);
    asm volatile("cp.async.cg.shared.global [%0], [%1], 16;\n" :: "r"(s), "l"(gmem));
}
#define CP_COMMIT() asm volatile("cp.async.commit_group;\n" ::: "memory")
#define CP_WAIT()   asm volatile("cp.async.wait_group 3;\n" ::: "memory")

// Tile load: 128 rows x 16 b32 from plain [row][k] global; XOR-swizzled smem:
// b32 slot = row*16 + (kc ^ ((row>>1)&3))*4.  Warp = 8 rows x 4 kc: each 8-lane
// phase covers 2 rows x 4 kc = quartets {4(r&1)+kc^swz} -> all 8 distinct.
// Global: 2 x 64B contiguous per 8 lanes (fully coalesced).
__device__ __forceinline__ void load_tile_async(unsigned* sm, const unsigned* g, int tid) {
    #pragma unroll
    for (int i = 0; i < 2; i++) {
        int c = tid + i * 256;          // 0..511
        int row = c >> 2, kc = c & 3;
        int swz = (row >> 1) & 3;
        cp_async16(sm + row * 16 + ((kc ^ swz) << 2),
                   g + (size_t)row * HD2 + kc * 4);
    }
}

// mma over one BK=32 tile using LDSM fragments; warp tile 64x32 (grid 2x4).
// offA/offB are per-lane byte offsets precomputed by the caller.
__device__ __forceinline__ void compute_rr(unsigned aBase, unsigned bBase,
                                           const unsigned offA[4][2],
                                           const unsigned offB[2][2],
                                           float acc[4][4][4]) {
    #pragma unroll
    for (int ks = 0; ks < 2; ks++) {
        unsigned b0[4], b1[4];
        ldsm_x4(b0, bBase + offB[0][ks]);
        ldsm_x4(b1, bBase + offB[1][ks]);
        #pragma unroll
        for (int mt = 0; mt < 4; mt++) {
            unsigned a[4];
            ldsm_x4(a, aBase + offA[mt][ks]);
            mma_bf16(acc[mt][0], a, b0);
            mma_bf16(acc[mt][1], a, b0 + 2);
            mma_bf16(acc[mt][2], a, b1);
            mma_bf16(acc[mt][3], a, b1 + 2);
        }
    }
}

// Per-lane LDSM address offsets (bytes) within a stage.
// A (m16k16 frag, x4): lanes 0-7 rows m+0..7 @k-lo, 8-15 rows m+8..15 @k-lo,
// 16-23 rows m+0..7 @k-hi, 24-31 rows m+8..15 @k-hi.
__device__ __forceinline__ void make_offA(unsigned offA[4][2], int wm, int lane) {
    int rl  = (lane & 7) + ((lane >> 3) & 1) * 8;
    int k8  = (lane >> 4) & 1;
    #pragma unroll
    for (int mt = 0; mt < 4; mt++) {
        int row = wm * 64 + mt * 16 + rl;
        int swz = (row >> 1) & 3;
        #pragma unroll
        for (int ks = 0; ks < 2; ks++) {
            int kc = ks * 2 + k8;
            offA[mt][ks] = (unsigned)(row * 64 + ((kc ^ swz) << 4));
        }
    }
}
// B (two n8k16 frags, x4): lanes 0-7 cols n+0..7 @k-lo, 8-15 cols n+0..7 @k-hi,
// 16-23 cols n+8..15 @k-lo, 24-31 cols n+8..15 @k-hi  -> regs {b0,b1},{b2,b3}.
__device__ __forceinline__ void make_offB(unsigned offB[2][2], int wn, int lane) {
    int nl  = (lane & 7) + ((lane >> 4) & 1) * 8;
    int k8  = (lane >> 3) & 1;
    #pragma unroll
    for (int np = 0; np < 2; np++) {
        int col = wn * 32 + np * 16 + nl;
        int swz = (col >> 1) & 3;
        #pragma unroll
        for (int ks = 0; ks < 2; ks++) {
            int kc = ks * 2 + k8;
            offB[np][ks] = (unsigned)(col * 64 + ((kc ^ swz) << 4));
        }
    }
}

// ---------------------------------------------------------------------------
// Kernel 0a: zero col-stat accumulators and the output buffer
// ---------------------------------------------------------------------------
__global__ void init_stats_kernel(float* out, int out_n) {
    int i = blockIdx.x * blockDim.x + threadIdx.x;
    if (i < BATCH * LA) {
        g_colMaxBits[i] = 0u;
        g_colSum[i] = 0.0f;
    }
    if (i < out_n) out[i] = 0.0f;
}

// ---------------------------------------------------------------------------
// Kernel 0b: convert q, a -> plain bf16x2
// ---------------------------------------------------------------------------
#define NQ4 (BATCH * LQ * HDIM / 4)
#define NA4 (BATCH * LA * HDIM / 4)

__global__ __launch_bounds__(256) void convert_qa_kernel(const float* __restrict__ q,
                                                         const float* __restrict__ a) {
    int stride = gridDim.x * blockDim.x;
    for (int i = blockIdx.x * blockDim.x + threadIdx.x; i < NQ4 + NA4; i += stride) {
        const float4* src;
        uint2* dst;
        if (i < NQ4) {
            src = (const float4*)q + i;
            dst = (uint2*)g_qt + i;
        } else {
            src = (const float4*)a + (i - NQ4);
            dst = (uint2*)g_at + (i - NQ4);
        }
        float4 v = *src;
        uint2 w;
        w.x = pack_bf16(v.x, v.y);
        w.y = pack_bf16(v.z, v.w);
        *dst = w;
    }
}

// ---------------------------------------------------------------------------
// Kernel 0c: U [k][n] fp32 -> g_Ut [n][k] plain bf16x2
// ---------------------------------------------------------------------------
__global__ __launch_bounds__(256) void convert_U_kernel(const float* __restrict__ U) {
    int i = blockIdx.x * blockDim.x + threadIdx.x;
    if (i >= HDIM * HD2) return;
    int n  = i >> 8;
    int ko = i & 255;
    int k0 = 2 * ko;
    g_Ut[i] = pack_bf16(U[(size_t)k0 * HDIM + n], U[(size_t)(k0 + 1) * HDIM + n]);
}

// ---------------------------------------------------------------------------
// Kernel 1: qU = q @ U  (bf16 mma, LDSM frags, 5-stage cp.async pipeline)
// ---------------------------------------------------------------------------
__global__ __launch_bounds__(256, 2) void gemm_qU_tc() {
    extern __shared__ unsigned dsm[];
    unsigned* sA = dsm;                           // [NSTAGE][STAGE_U32]
    unsigned* sB = dsm + NSTAGE * STAGE_U32;

    const int tid  = threadIdx.x;
    const int lane = tid & 31;
    const int wm   = (tid >> 5) >> 2;
    const int wn   = (tid >> 5) & 3;
    const int m0   = blockIdx.y * BM;
    const int n0   = blockIdx.x * BN;

    const unsigned* gA = g_qt + (size_t)m0 * HD2;
    const unsigned* gB = g_Ut + (size_t)n0 * HD2;

    unsigned offA[4][2], offB[2][2];
    make_offA(offA, wm, lane);
    make_offB(offB, wn, lane);
    const unsigned aU = (unsigned)__cvta_generic_to_shared(sA);
    const unsigned bU = (unsigned)__cvta_generic_to_shared(sB);

    float acc[4][4][4] = {};

    #pragma unroll
    for (int s = 0; s < NSTAGE - 1; s++) {
        load_tile_async(sA + s * STAGE_U32, gA + s * 16, tid);
        load_tile_async(sB + s * STAGE_U32, gB + s * 16, tid);
        CP_COMMIT();
    }

    for (int kt = 0; kt < NKT; kt++) {
        CP_WAIT();
        __syncthreads();
        int pf = kt + NSTAGE - 1;
        if (pf < NKT) {
            load_tile_async(sA + (pf % NSTAGE) * STAGE_U32, gA + pf * 16, tid);
            load_tile_async(sB + (pf % NSTAGE) * STAGE_U32, gB + pf * 16, tid);
        }
        CP_COMMIT();
        int st = (kt % NSTAGE) * STAGE_BYTES;
        compute_rr(aU + st, bU + st, offA, offB, acc);
    }

    // epilogue: plain bf16 write, slot = col/2
    #pragma unroll
    for (int mt = 0; mt < 4; mt++) {
        int row = m0 + wm * 64 + mt * 16 + (lane >> 2);
        #pragma unroll
        for (int nt = 0; nt < 4; nt++) {
            int slot = (n0 >> 1) + wn * 16 + nt * 4 + (lane & 3);
            g_qU[(size_t)row * HD2 + slot]       = pack_bf16(acc[mt][nt][0], acc[mt][nt][1]);
            g_qU[(size_t)(row + 8) * HD2 + slot] = pack_bf16(acc[mt][nt][2], acc[mt][nt][3]);
        }
    }
}

// ---------------------------------------------------------------------------
// Kernel 2: fused X = qU @ a^T + sigmoid/exp + row & col stats
// Flat 128-tile pipeline over (j0 x kt); epilogue every 16 tiles
// ---------------------------------------------------------------------------
__global__ __launch_bounds__(256, 2) void fused_X_tc(const float* __restrict__ q_mask,
                                                     const float* __restrict__ a_mask) {
    extern __shared__ unsigned dsm[];
    unsigned* sA = dsm;
    unsigned* sB = dsm + NSTAGE * STAGE_U32;

    const int tid  = threadIdx.x;
    const int lane = tid & 31;
    const int wm   = (tid >> 5) >> 2;
    const int wn   = (tid >> 5) & 3;
    const int b    = blockIdx.y;
    const int i0   = blockIdx.x * BM;

    const unsigned* qUb = g_qU + ((size_t)b * LQ + i0) * HD2;
    const unsigned* ab  = g_at + (size_t)b * LA * HD2;

    unsigned offA[4][2], offB[2][2];
    make_offA(offA, wm, lane);
    make_offB(offB, wn, lane);
    const unsigned aU = (unsigned)__cvta_generic_to_shared(sA);
    const unsigned bU = (unsigned)__cvta_generic_to_shared(sB);

    float qm[4][2];
    #pragma unroll
    for (int mt = 0; mt < 4; mt++) {
        int r = i0 + wm * 64 + mt * 16 + (lane >> 2);
        qm[mt][0] = q_mask[b * LQ + r];
        qm[mt][1] = q_mask[b * LQ + r + 8];
    }

    float rowMax[4][2] = {};
    float rowSum[4][2] = {};
    float acc[4][4][4] = {};

    const int NT = (LA / BN) * NKT;   // 128 tiles

    #pragma unroll
    for (int s = 0; s < NSTAGE - 1; s++) {
        load_tile_async(sA + s * STAGE_U32, qUb + s * 16, tid);
        load_tile_async(sB + s * STAGE_U32, ab + s * 16, tid);   // j = 0
        CP_COMMIT();
    }

    for (int t = 0; t < NT; t++) {
        CP_WAIT();
        __syncthreads();
        int pf = t + NSTAGE - 1;
        if (pf < NT) {
            int pj = pf >> 4, pk = pf & 15;
            load_tile_async(sA + (pf % NSTAGE) * STAGE_U32, qUb + pk * 16, tid);
            load_tile_async(sB + (pf % NSTAGE) * STAGE_U32,
                            ab + (size_t)pj * BN * HD2 + pk * 16, tid);
        }
        CP_COMMIT();
        int st = (t % NSTAGE) * STAGE_BYTES;
        compute_rr(aU + st, bU + st, offA, offB, acc);

        if ((t & 15) == 15) {
            // ---- epilogue for j0 = (t>>4)*BN ----
            const int j0 = (t >> 4) * BN;
            // scratch aliases the just-consumed stage; the next write into this
            // stage is iteration t+1's prefetch (pf = t+5 -> stage t%5), which
            // is after that iteration's __syncthreads
            float* redM = (float*)(sA + (t % NSTAGE) * STAGE_U32);
            float* redS = redM + 512;

            float am[4][2];
            #pragma unroll
            for (int nt = 0; nt < 4; nt++) {
                int c = j0 + wn * 32 + nt * 8 + (lane & 3) * 2;
                am[nt][0] = __ldg(&a_mask[b * LA + c]);
                am[nt][1] = __ldg(&a_mask[b * LA + c + 1]);
            }

            float cMax[4][2] = {};
            float cSum[4][2] = {};

            #pragma unroll
            for (int mt = 0; mt < 4; mt++) {
                #pragma unroll
                for (int nt = 0; nt < 4; nt++) {
                    #pragma unroll
                    for (int e = 0; e < 4; e++) {
                        float X = acc[mt][nt][e];
                        bool valid = (qm[mt][e >> 1] * am[nt][e & 1]) > 0.0f;
                        float I = valid ? __fdividef(1.0f, 1.0f + __expf(-X)) : 0.0f;
                        float ee = __expf(I);
                        rowMax[mt][e >> 1] = fmaxf(rowMax[mt][e >> 1], I);
                        rowSum[mt][e >> 1] += ee;
                        cMax[nt][e & 1] = fmaxf(cMax[nt][e & 1], I);
                        cSum[nt][e & 1] += ee;
                        acc[mt][nt][e] = 0.0f;   // reset for next j-tile
                    }
                }
            }

            __syncthreads();   // stage fully consumed before scratch reuse
            #pragma unroll
            for (int nt = 0; nt < 4; nt++) {
                #pragma unroll
                for (int j = 0; j < 2; j++) {
                    float m = cMax[nt][j], s = cSum[nt][j];
                    #pragma unroll
                    for (int off = 4; off < 32; off <<= 1) {
                        m = fmaxf(m, __shfl_xor_sync(0xffffffffu, m, off));
                        s += __shfl_xor_sync(0xffffffffu, s, off);
                    }
                    if (lane < 4) {
                        int colL = wn * 32 + nt * 8 + 2 * lane + j;
                        redM[wm * 128 + colL] = m;
                        redS[wm * 128 + colL] = s;
                    }
                }
            }
            __syncthreads();
            if (tid < 128) {
                float m = fmaxf(redM[tid], redM[128 + tid]);
                float s = redS[tid] + redS[128 + tid];
                int cj = b * LA + j0 + tid;
                atomicMax(&g_colMaxBits[cj], __float_as_uint(m));
                atomicAdd(&g_colSum[cj], s);
            }
            __syncthreads();   // scratch released before next iteration's loads
        }
    }

    // ---- final row reduction ----
    {
        float* redM = (float*)dsm;
        float* redS = redM + 512;
        #pragma unroll
        for (int mt = 0; mt < 4; mt++) {
            #pragma unroll
            for (int e = 0; e < 2; e++) {
                float m = rowMax[mt][e], s = rowSum[mt][e];
                #pragma unroll
                for (int off = 1; off < 4; off <<= 1) {
                    m = fmaxf(m, __shfl_xor_sync(0xffffffffu, m, off));
                    s += __shfl_xor_sync(0xffffffffu, s, off);
                }
                if ((lane & 3) == 0) {
                    int rowL = wm * 64 + mt * 16 + (lane >> 2) + e * 8;
                    redM[wn * 128 + rowL] = m;
                    redS[wn * 128 + rowL] = s;
                }
            }
        }
        __syncthreads();
        if (tid < 128) {
            float m = redM[tid], s = redS[tid];
            #pragma unroll
            for (int w = 1; w < 4; w++) {
                m = fmaxf(m, redM[w * 128 + tid]);
                s += redS[w * 128 + tid];
            }
            g_rowAtt[b * LQ + i0 + tid] = __expf(m) / s;
        }
    }
}

// ---------------------------------------------------------------------------
// Kernel 3: weighted reductions, 8 L-segments with atomicAdd (exact fp32 q/a)
// ---------------------------------------------------------------------------
__global__ __launch_bounds__(512) void finalize_tc(const float* __restrict__ q,
                                                   const float* __restrict__ a,
                                                   float* __restrict__ out) {
    __shared__ float attS[128];
    const int b     = blockIdx.x;
    const int which = blockIdx.y;
    const int seg   = blockIdx.z;   // 0..7
    const int h     = threadIdx.x;
    const int l0    = seg * 128;

    if (h < 128) {
        int l = l0 + h;
        if (which == 0) {
            attS[h] = g_rowAtt[b * LQ + l];
        } else {
            float m = __uint_as_float(g_colMaxBits[b * LA + l]);
            attS[h] = __expf(m) / g_colSum[b * LA + l];
        }
    }
    __syncthreads();

    const float* src = ((which == 0) ? q : a) + (size_t)b * LQ * HDIM + (size_t)l0 * HDIM;

    float a0 = 0.f, a1 = 0.f, a2 = 0.f, a3 = 0.f;
    #pragma unroll 4
    for (int l = 0; l < 128; l += 4) {
        a0 = fmaf(src[(size_t)(l + 0) * HDIM + h], attS[l + 0], a0);
        a1 = fmaf(src[(size_t)(l + 1) * HDIM + h], attS[l + 1], a1);
        a2 = fmaf(src[(size_t)(l + 2) * HDIM + h], attS[l + 2], a2);
        a3 = fmaf(src[(size_t)(l + 3) * HDIM + h], attS[l + 3], a3);
    }
    atomicAdd(&out[(size_t)which * BATCH * HDIM + b * HDIM + h], (a0 + a1) + (a2 + a3));
}

// ---------------------------------------------------------------------------
extern "C" void kernel_launch(void* const* d_in, const int* in_sizes, int n_in,
                              void* d_out, int out_size) {
    const float* q      = (const float*)d_in[0];
    const float* a      = (const float*)d_in[1];
    const float* U      = (const float*)d_in[2];
    const float* q_mask = (const float*)d_in[3];
    const float* a_mask = (const float*)d_in[4];
    float* out = (float*)d_out;

    const int smem_sz = NSTAGE * 2 * STAGE_U32 * sizeof(unsigned);   // 81920
    cudaFuncSetAttribute(gemm_qU_tc, cudaFuncAttributeMaxDynamicSharedMemorySize, smem_sz);
    cudaFuncSetAttribute(fused_X_tc, cudaFuncAttributeMaxDynamicSharedMemorySize, smem_sz);

    init_stats_kernel<<<(BATCH * LA + 255) / 256, 256>>>(out, out_size);
    convert_qa_kernel<<<4096, 256>>>(q, a);
    convert_U_kernel<<<(HDIM * HD2 + 255) / 256, 256>>>(U);

    dim3 g1(HDIM / BN, (BATCH * LQ) / BM);   // (4, 256)
    gemm_qU_tc<<<g1, 256, smem_sz>>>();

    dim3 g2(LQ / BM, BATCH);                 // (8, 32)
    fused_X_tc<<<g2, 256, smem_sz>>>(q_mask, a_mask);

    dim3 g3(BATCH, 2, 8);
    finalize_tc<<<g3, 512>>>(q, a, out);
}